// round 12
// baseline (speedup 1.0000x reference)
#include <cuda_runtime.h>

// FourierELU on x[32,64,8,64,64], axis 2 (size 8):
//   rfft(8) -> pad to 9 bins -> irfft(16) -> elu -> rfft(16) -> keep 5 -> irfft(8)
// Closed form: y = B * elu(A * x):
//   alt        = sum_n (-1)^n x[n]
//   xup[2m]    = 0.5*x[m] + (-1)^m * alt/16
//   xup[2t+1]  = sum_n d[(t-n)&7] * x[n]          (8-pt symmetric circulant)
//   y[m]       = elu(xup[2m]) + sum_t e[(m-t)&7] * elu(xup[2t+1]), e[s]=2*d[(s-1)&7]
//
// FINAL — measured-best configuration (81.5-82.1 us wall band, ncu 74.8 us,
// DRAM 81.1% = ~96% of realistic mixed-R/W HBM ceiling):
//   R2: packed f32x2 (SASS FFMA2) for all linear chains.
//   R3: 2 pixels/thread (LDG.64, 256B/warp fully coalesced).
//   R4: symmetry pair-sum factorization of both circulants; gather form with
//       immediate interleaved stores; 128-thr blocks, 9 CTAs/SM.
// Session verdicts (R5-R11): cache hints (.cs on loads OR stores) break ptxas
// load batching / L2 write combining -> regress; persistent grid regresses
// (loop-carried scheduling kills front-batched MLP); occupancy beyond ~49%
// and fewer math ops are neutral. Kernel sits at the sustained-HBM floor:
// 536.9 MB mandatory traffic @ ~6.5 TB/s sustained ~= 82 us.

#define PLANE2  2048            // (64*64)/2 f32x2 per plane
#define OUTER   2048            // 32*64
#define TOTAL2  (OUTER * PLANE2)
#define NTHREADS 128

typedef unsigned long long u64;

__device__ __forceinline__ u64 bc(float f) {
    unsigned u = __float_as_uint(f);
    return ((u64)u << 32) | (u64)u;
}

__device__ __forceinline__ u64 f2fma(u64 a, u64 b, u64 c) {
    u64 d;
    asm("fma.rn.f32x2 %0, %1, %2, %3;" : "=l"(d) : "l"(a), "l"(b), "l"(c));
    return d;
}
__device__ __forceinline__ u64 f2mul(u64 a, u64 b) {
    u64 d;
    asm("mul.rn.f32x2 %0, %1, %2;" : "=l"(d) : "l"(a), "l"(b));
    return d;
}
__device__ __forceinline__ u64 f2add(u64 a, u64 b) {
    u64 d;
    asm("add.rn.f32x2 %0, %1, %2;" : "=l"(d) : "l"(a), "l"(b));
    return d;
}

__device__ __forceinline__ float eluf(float v) {
    return v > 0.0f ? v : (__expf(v) - 1.0f);
}

__device__ __forceinline__ u64 elu2(u64 v) {
    float a, b;
    asm("mov.b64 {%0, %1}, %2;" : "=f"(a), "=f"(b) : "l"(v));
    a = eluf(a);
    b = eluf(b);
    u64 r;
    asm("mov.b64 %0, {%1, %2};" : "=l"(r) : "f"(a), "f"(b));
    return r;
}

__global__ void __launch_bounds__(NTHREADS, 9)
fourier_elu_kernel(const u64* __restrict__ in, u64* __restrict__ out) {
    const int tid   = blockIdx.x * NTHREADS + threadIdx.x;   // 0 .. TOTAL2-1
    const int outer = tid >> 11;
    const int inner = tid & 2047;
    const int base  = outer * (8 * PLANE2) + inner;

    const float D0 =  0.31420871834f;
    const float D1 = -0.09353786017f;
    const float D2 =  0.04176116486f;
    const float D3 = -0.01243202296f;
    const u64 CD0 = bc(D0), CD1 = bc(D1), CD2 = bc(D2), CD3 = bc(D3);
    const u64 CE0 = bc(2.0f*D0), CE1 = bc(2.0f*D1),
              CE2 = bc(2.0f*D2), CE3 = bc(2.0f*D3);
    const u64 HALF = bc(0.5f);
    const u64 NEG1 = bc(-1.0f);
    const u64 SC_P = bc( 0.0625f);
    const u64 SC_N = bc(-0.0625f);

    // Load 8 group samples (one f32x2 each), coalesced LDG.64, front-batched.
    u64 x[8];
#pragma unroll
    for (int g = 0; g < 8; g++) {
        x[g] = in[base + g * PLANE2];
    }

    // Alternating sum (Nyquist bin contribution).
    u64 alt = x[0];
#pragma unroll
    for (int n = 1; n < 8; n++) {
        if (n & 1) alt = f2fma(x[n], NEG1, alt);
        else       alt = f2add(alt, x[n]);
    }
    const u64 ap = f2mul(alt, SC_P);
    const u64 an = f2mul(alt, SC_N);

    // Odd upsamples via symmetric circulant; t and t+4 share pair sums
    // P_j = x[n] + x[n'] with n + n' == 2t+1 (mod 8).
    u64 s[8];
#pragma unroll
    for (int t = 0; t < 4; t++) {
        u64 P0 = f2add(x[t],           x[(t + 1) & 7]);
        u64 P1 = f2add(x[(t + 7) & 7], x[(t + 2) & 7]);
        u64 P2 = f2add(x[(t + 6) & 7], x[(t + 3) & 7]);
        u64 P3 = f2add(x[(t + 5) & 7], x[(t + 4) & 7]);
        u64 a = f2mul(CD0, P0);
        a = f2fma(CD1, P1, a);
        a = f2fma(CD2, P2, a);
        a = f2fma(CD3, P3, a);
        u64 b = f2mul(CD3, P0);
        b = f2fma(CD2, P1, b);
        b = f2fma(CD1, P2, b);
        b = f2fma(CD0, P3, b);
        s[t]     = elu2(a);
        s[t + 4] = elu2(b);
    }

    // Gather outputs; m and m+4 share pair sums R_j of elu'd odd samples
    // (e[s] = e[(1-s)&7]). Even-upsample identity path folded in as the
    // accumulator seed. Store immediately (no acc array).
#pragma unroll
    for (int m = 0; m < 4; m++) {
        u64 R0 = f2add(s[m],           s[(m + 7) & 7]);
        u64 R1 = f2add(s[(m + 6) & 7], s[(m + 1) & 7]);
        u64 R2 = f2add(s[(m + 5) & 7], s[(m + 2) & 7]);
        u64 R3 = f2add(s[(m + 4) & 7], s[(m + 3) & 7]);

        u64 e0 = elu2(f2fma(x[m],     HALF, (m & 1) ? an : ap));
        u64 e4 = elu2(f2fma(x[m + 4], HALF, (m & 1) ? an : ap));

        u64 y0 = f2fma(CE0, R0, e0);
        y0 = f2fma(CE1, R1, y0);
        y0 = f2fma(CE2, R2, y0);
        y0 = f2fma(CE3, R3, y0);

        u64 y4 = f2fma(CE3, R0, e4);
        y4 = f2fma(CE2, R1, y4);
        y4 = f2fma(CE1, R2, y4);
        y4 = f2fma(CE0, R3, y4);

        out[base + m * PLANE2]       = y0;
        out[base + (m + 4) * PLANE2] = y4;
    }
}

extern "C" void kernel_launch(void* const* d_in, const int* in_sizes, int n_in,
                              void* d_out, int out_size) {
    (void)in_sizes; (void)n_in; (void)out_size;
    const u64* in2 = reinterpret_cast<const u64*>(d_in[0]);
    u64*       o2  = reinterpret_cast<u64*>(d_out);
    fourier_elu_kernel<<<TOTAL2 / NTHREADS, NTHREADS>>>(in2, o2);
}

// round 13
// speedup vs baseline: 1.2065x; 1.2065x over previous
#include <cuda_runtime.h>

// FourierELU on x[32,64,8,64,64], axis 2 (size 8):
//   rfft(8) -> pad to 9 bins -> irfft(16) -> elu -> rfft(16) -> keep 5 -> irfft(8)
// Closed form: y = B * elu(A * x):
//   alt        = sum_n (-1)^n x[n]
//   xup[2m]    = 0.5*x[m] + (-1)^m * alt/16
//   xup[2t+1]  = sum_n d[(t-n)&7] * x[n]          (8-pt symmetric circulant)
//   y[m]       = elu(xup[2m]) + sum_t e[(m-t)&7] * elu(xup[2t+1]), e[s]=2*d[(s-1)&7]
//
// FINAL: minimum-issue-slot body for DVFS robustness.
// R12 showed identical SASS swinging 82->99 us with SM-clock throttle
// (issue 67->84%, DRAM 81->64%): under throttle the kernel goes
// compute-bound, so wall time is minimax'd by the fewest-instruction body.
//   R2: packed f32x2 (SASS FFMA2) for all linear chains.
//   R3: 2 pixels/thread (LDG.64, 256B/warp fully coalesced).
//   R4: symmetry pair-sum factorization of both circulants; gather form.
//   R6: 4-op ELU  elu(v) = max(v, ex2(min(v*log2e,0))-1), packed log2e mul
//       (40 regs, issue 58.7% at full clock vs 67.5% for the FSEL body).
// Verdicts: cache hints regress (break load batching/write combining);
// persistent grid regresses (kills front-batched MLP); at full clock the
// kernel sits at the sustained-HBM floor (536.9 MB @ ~6.5 TB/s ~= 82 us).

#define PLANE2  2048            // (64*64)/2 f32x2 per plane
#define OUTER   2048            // 32*64
#define TOTAL2  (OUTER * PLANE2)
#define NTHREADS 128

typedef unsigned long long u64;

__device__ __forceinline__ u64 bc(float f) {
    unsigned u = __float_as_uint(f);
    return ((u64)u << 32) | (u64)u;
}

__device__ __forceinline__ u64 f2fma(u64 a, u64 b, u64 c) {
    u64 d;
    asm("fma.rn.f32x2 %0, %1, %2, %3;" : "=l"(d) : "l"(a), "l"(b), "l"(c));
    return d;
}
__device__ __forceinline__ u64 f2mul(u64 a, u64 b) {
    u64 d;
    asm("mul.rn.f32x2 %0, %1, %2;" : "=l"(d) : "l"(a), "l"(b));
    return d;
}
__device__ __forceinline__ u64 f2add(u64 a, u64 b) {
    u64 d;
    asm("add.rn.f32x2 %0, %1, %2;" : "=l"(d) : "l"(a), "l"(b));
    return d;
}

__device__ __forceinline__ float ex2f(float x) {
    float r;
    asm("ex2.approx.f32 %0, %1;" : "=f"(r) : "f"(x));
    return r;
}

// elu(v) = max(v, exp(min(v,0)) - 1); log2e scaling hoisted into one packed
// mul (min commutes with positive scaling). 4 scalar ops/lane:
// FMNMX, MUFU.EX2, FADD, FMNMX — no predicate chain.
//   v>0: ex2 term is 0, max picks v.  v<=0: exp(v)-1 >= v, max picks it.
__device__ __forceinline__ u64 elu2(u64 v, u64 LOG2E) {
    u64 w = f2mul(v, LOG2E);
    float v0, v1, w0, w1;
    asm("mov.b64 {%0, %1}, %2;" : "=f"(v0), "=f"(v1) : "l"(v));
    asm("mov.b64 {%0, %1}, %2;" : "=f"(w0), "=f"(w1) : "l"(w));
    float r0 = fmaxf(v0, ex2f(fminf(w0, 0.0f)) - 1.0f);
    float r1 = fmaxf(v1, ex2f(fminf(w1, 0.0f)) - 1.0f);
    u64 r;
    asm("mov.b64 %0, {%1, %2};" : "=l"(r) : "f"(r0), "f"(r1));
    return r;
}

__global__ void __launch_bounds__(NTHREADS, 9)
fourier_elu_kernel(const u64* __restrict__ in, u64* __restrict__ out) {
    const int tid   = blockIdx.x * NTHREADS + threadIdx.x;   // 0 .. TOTAL2-1
    const int outer = tid >> 11;
    const int inner = tid & 2047;
    const int base  = outer * (8 * PLANE2) + inner;

    const float D0 =  0.31420871834f;
    const float D1 = -0.09353786017f;
    const float D2 =  0.04176116486f;
    const float D3 = -0.01243202296f;
    const u64 CD0 = bc(D0), CD1 = bc(D1), CD2 = bc(D2), CD3 = bc(D3);
    const u64 CE0 = bc(2.0f*D0), CE1 = bc(2.0f*D1),
              CE2 = bc(2.0f*D2), CE3 = bc(2.0f*D3);
    const u64 HALF   = bc(0.5f);
    const u64 NEG1   = bc(-1.0f);
    const u64 SC_P   = bc( 0.0625f);
    const u64 SC_N   = bc(-0.0625f);
    const u64 LOG2E  = bc(1.4426950408889634f);

    // Load 8 group samples (one f32x2 each), coalesced LDG.64, front-batched.
    u64 x[8];
#pragma unroll
    for (int g = 0; g < 8; g++) {
        x[g] = in[base + g * PLANE2];
    }

    // Alternating sum (Nyquist bin contribution).
    u64 alt = x[0];
#pragma unroll
    for (int n = 1; n < 8; n++) {
        if (n & 1) alt = f2fma(x[n], NEG1, alt);
        else       alt = f2add(alt, x[n]);
    }
    const u64 ap = f2mul(alt, SC_P);
    const u64 an = f2mul(alt, SC_N);

    // Odd upsamples via symmetric circulant; t and t+4 share pair sums
    // P_j = x[n] + x[n'] with n + n' == 2t+1 (mod 8).
    u64 s[8];
#pragma unroll
    for (int t = 0; t < 4; t++) {
        u64 P0 = f2add(x[t],           x[(t + 1) & 7]);
        u64 P1 = f2add(x[(t + 7) & 7], x[(t + 2) & 7]);
        u64 P2 = f2add(x[(t + 6) & 7], x[(t + 3) & 7]);
        u64 P3 = f2add(x[(t + 5) & 7], x[(t + 4) & 7]);
        u64 a = f2mul(CD0, P0);
        a = f2fma(CD1, P1, a);
        a = f2fma(CD2, P2, a);
        a = f2fma(CD3, P3, a);
        u64 b = f2mul(CD3, P0);
        b = f2fma(CD2, P1, b);
        b = f2fma(CD1, P2, b);
        b = f2fma(CD0, P3, b);
        s[t]     = elu2(a, LOG2E);
        s[t + 4] = elu2(b, LOG2E);
    }

    // Gather outputs; m and m+4 share pair sums R_j of elu'd odd samples
    // (e[s] = e[(1-s)&7]). Even-upsample identity path is the seed.
    // Store immediately (loads of next ELU chain overlap prior stores).
#pragma unroll
    for (int m = 0; m < 4; m++) {
        u64 R0 = f2add(s[m],           s[(m + 7) & 7]);
        u64 R1 = f2add(s[(m + 6) & 7], s[(m + 1) & 7]);
        u64 R2 = f2add(s[(m + 5) & 7], s[(m + 2) & 7]);
        u64 R3 = f2add(s[(m + 4) & 7], s[(m + 3) & 7]);

        u64 e0 = elu2(f2fma(x[m],     HALF, (m & 1) ? an : ap), LOG2E);
        u64 e4 = elu2(f2fma(x[m + 4], HALF, (m & 1) ? an : ap), LOG2E);

        u64 y0 = f2fma(CE0, R0, e0);
        y0 = f2fma(CE1, R1, y0);
        y0 = f2fma(CE2, R2, y0);
        y0 = f2fma(CE3, R3, y0);

        u64 y4 = f2fma(CE3, R0, e4);
        y4 = f2fma(CE2, R1, y4);
        y4 = f2fma(CE1, R2, y4);
        y4 = f2fma(CE0, R3, y4);

        out[base + m * PLANE2]       = y0;
        out[base + (m + 4) * PLANE2] = y4;
    }
}

extern "C" void kernel_launch(void* const* d_in, const int* in_sizes, int n_in,
                              void* d_out, int out_size) {
    (void)in_sizes; (void)n_in; (void)out_size;
    const u64* in2 = reinterpret_cast<const u64*>(d_in[0]);
    u64*       o2  = reinterpret_cast<u64*>(d_out);
    fourier_elu_kernel<<<TOTAL2 / NTHREADS, NTHREADS>>>(in2, o2);
}